// round 7
// baseline (speedup 1.0000x reference)
#include <cuda_runtime.h>
#include <cuda_bf16.h>
#include <cstdint>

// ---------------------------------------------------------------------------
// label_loss: B=4.19M elements -> 3 scalars. Memory-bound (218 MB read).
// R7: cp.async.bulk (UBLKCP) double-buffered GMEM->SMEM pipeline.
// Rationale: per-lane LDG at stride 48B inflates L1tex wavefronts 3x and
// holds DRAM latency in registers; 48 warps/SM (RF cap at 40 regs) pins
// DRAM at ~69%. Bulk copies stream contiguous 13KB tiles at the LTS cap;
// compute reads SMEM. R6 champion: 41.5us, DRAM=69.4%.
// ---------------------------------------------------------------------------

#define NBLK 888        // 148 SMs * 6 CTAs -> one wave
#define NTHR 256
#define TILE 256        // elements per tile
#define LBYTES (TILE * 24)              // label/est bytes per tile (6144)
#define MBYTES (TILE * 4)               // mix bytes per tile (1024)
#define TXBYTES (2 * LBYTES + MBYTES)   // 13312

static __device__ float g_part[5][NBLK];
static __device__ int   g_count = 0;

__device__ __forceinline__ uint32_t s2u(const void* p) {
    uint32_t a;
    asm("{ .reg .u64 t; cvta.to.shared.u64 t, %1; cvt.u32.u64 %0, t; }"
        : "=r"(a) : "l"(p));
    return a;
}

__device__ __forceinline__ void mbar_init(uint32_t mb, uint32_t cnt) {
    asm volatile("mbarrier.init.shared.b64 [%0], %1;" :: "r"(mb), "r"(cnt) : "memory");
}

__device__ __forceinline__ void mbar_expect_tx(uint32_t mb, uint32_t bytes) {
    asm volatile("mbarrier.arrive.expect_tx.shared.b64 _, [%0], %1;"
                 :: "r"(mb), "r"(bytes) : "memory");
}

__device__ __forceinline__ void bulk_ld(uint32_t dst, const void* src,
                                        uint32_t bytes, uint32_t mb) {
    asm volatile(
        "cp.async.bulk.shared::cta.global.mbarrier::complete_tx::bytes "
        "[%0], [%1], %2, [%3];"
        :: "r"(dst), "l"(src), "r"(bytes), "r"(mb) : "memory");
}

__device__ __forceinline__ void mbar_wait(uint32_t mb, uint32_t phase) {
    uint32_t done = 0;
    while (!done) {
        asm volatile(
            "{\n\t.reg .pred p;\n\t"
            "mbarrier.try_wait.parity.acquire.cta.shared::cta.b64 p, [%1], %2, 0x989680;\n\t"
            "selp.b32 %0, 1, 0, p;\n\t}"
            : "=r"(done) : "r"(mb), "r"(phase) : "memory");
    }
}

__device__ __forceinline__ float angdiff_deg(float x1, float y1, float x2, float y2) {
    // |atan2(y1,x1) - atan2(y2,x2)| wrapped to [0, 180], in degrees.
    float cr = fmaf(y1, x2, -x1 * y2);
    float dt = fmaf(x1, x2,  y1 * y2);
    float p  = fabsf(cr);
    float q  = fabsf(dt);
    float mx = fmaxf(fmaxf(p, q), 1e-38f);
    float mn = fminf(p, q);
    float r  = __fdividef(mn, mx);       // r in [0, 1]
    float t2 = r * r;
    const float D = 57.29577951308232f;  // rad -> deg folded into coefficients
    float pl;
    pl = fmaf(t2, -0.01172120f * D,  0.05265332f * D);
    pl = fmaf(t2, pl,           -0.11643287f * D);
    pl = fmaf(t2, pl,            0.19354346f * D);
    pl = fmaf(t2, pl,           -0.33262347f * D);
    pl = fmaf(t2, pl,            0.99997726f * D);
    float at = r * pl;                   // atan(mn/mx) in degrees, [0, 45]
    float a  = (p > q)      ? (90.0f  - at) : at;
    a        = (dt < 0.0f)  ? (180.0f - a ) : a;
    return a;
}

struct Acc { float S, M, A1, A2; };

__device__ __forceinline__ void proc(
    float l00, float l01, float l10, float l11, float l20, float l21,
    float e0, float e1, float e2, float e3, float e4, float e5,
    int m, Acc& a)
{
    float d0 = e0 - l00, d1 = e1 - l10, d2 = e2 - l20;
    float s11 = fmaf(d2, d2, fmaf(d1, d1, d0 * d0));
    float f0 = e3 - l01, f1 = e4 - l11, f2 = e5 - l21;
    float s22 = fmaf(f2, f2, fmaf(f1, f1, f0 * f0));
    float g0 = e0 - l01, g1 = e1 - l11, g2 = e2 - l21;
    float s12 = fmaf(g2, g2, fmaf(g1, g1, g0 * g0));
    float h0 = e3 - l00, h1 = e4 - l10, h2 = e5 - l20;
    float s21 = fmaf(h2, h2, fmaf(h1, h1, h0 * h0));

    a.S += s11;
    float mixed = fminf(s11 + s22, s12 + s21);  // /3 deferred to finalize
    a.M  += (m != 0) ? mixed : 0.0f;

    float a11 = angdiff_deg(l00, l10, e0, e1);
    float a22 = angdiff_deg(l01, l11, e3, e4);
    float a12 = angdiff_deg(l00, l10, e3, e4);
    float a21 = angdiff_deg(l01, l11, e0, e1);
    bool ud = (a11 + a22) < (a12 + a21);
    a.A1 += ud ? a11 : a12;
    a.A2 += ud ? a22 : a21;
}

__global__ void __launch_bounds__(NTHR, 6)
fused_kernel(const float* __restrict__ label, const float* __restrict__ est,
             const int* __restrict__ mix, float* __restrict__ out, int B)
{
    __shared__ __align__(128) float sL[2][TILE * 6];
    __shared__ __align__(128) float sE[2][TILE * 6];
    __shared__ __align__(128) int   sM[2][TILE];
    __shared__ __align__(8) unsigned long long mbar[2];

    const char* Lg = (const char*)label;
    const char* Eg = (const char*)est;
    const char* Mg = (const char*)mix;

    const int ntiles = B / TILE;
    const int tid = threadIdx.x;
    const int bid = blockIdx.x;

    if (tid == 0) {
        mbar_init(s2u(&mbar[0]), 1);
        mbar_init(s2u(&mbar[1]), 1);
    }
    __syncthreads();

    // Prologue: issue tiles bid (buf0) and bid+NBLK (buf1).
    if (tid == 0) {
        #pragma unroll
        for (int s = 0; s < 2; s++) {
            int g = bid + s * NBLK;
            if (g < ntiles) {
                uint32_t mb = s2u(&mbar[s]);
                mbar_expect_tx(mb, TXBYTES);
                bulk_ld(s2u(sL[s]), Lg + (size_t)g * LBYTES, LBYTES, mb);
                bulk_ld(s2u(sE[s]), Eg + (size_t)g * LBYTES, LBYTES, mb);
                bulk_ld(s2u(sM[s]), Mg + (size_t)g * MBYTES, MBYTES, mb);
            }
        }
    }

    Acc a{0.f, 0.f, 0.f, 0.f};
    int c0 = 0;
    int ph0 = 0, ph1 = 0;
    int s = 0;

    for (int g = bid; g < ntiles; g += NBLK) {
        uint32_t mb = s2u(&mbar[s]);
        int& ph = s ? ph1 : ph0;
        mbar_wait(mb, ph);
        ph ^= 1;

        // Compute element tid of tile g (stride-24B float2 reads: conflict-free).
        const float* Lp = &sL[s][tid * 6];
        const float* Ep = &sE[s][tid * 6];
        float2 La = *(const float2*)(Lp + 0);
        float2 Lb = *(const float2*)(Lp + 2);
        float2 Lc = *(const float2*)(Lp + 4);
        float2 Ea = *(const float2*)(Ep + 0);
        float2 Eb = *(const float2*)(Ep + 2);
        float2 Ec = *(const float2*)(Ep + 4);
        int m = sM[s][tid];
        proc(La.x, La.y, Lb.x, Lb.y, Lc.x, Lc.y,
             Ea.x, Ea.y, Eb.x, Eb.y, Ec.x, Ec.y, m, a);
        c0 += (m == 0);

        __syncthreads();   // all threads done reading buf s -> safe to refill

        int gn = g + 2 * NBLK;
        if (tid == 0 && gn < ntiles) {
            asm volatile("fence.proxy.async.shared::cta;" ::: "memory");
            mbar_expect_tx(mb, TXBYTES);
            bulk_ld(s2u(sL[s]), Lg + (size_t)gn * LBYTES, LBYTES, mb);
            bulk_ld(s2u(sE[s]), Eg + (size_t)gn * LBYTES, LBYTES, mb);
            bulk_ld(s2u(sM[s]), Mg + (size_t)gn * MBYTES, MBYTES, mb);
        }
        s ^= 1;
    }

    // Remainder elements (B % TILE != 0): direct loads by block 0.
    int rem = B - ntiles * TILE;
    if (rem && bid == 0 && tid < rem) {
        int i = ntiles * TILE + tid;
        const float* L = label + 6 * i;
        const float* E = est   + 6 * i;
        int m = mix[i];
        proc(L[0], L[1], L[2], L[3], L[4], L[5],
             E[0], E[1], E[2], E[3], E[4], E[5], m, a);
        c0 += (m == 0);
    }

    // Deterministic block reduction -> per-block float partials.
    float v[5] = {a.S, a.M, a.A1, a.A2, (float)c0};
    __shared__ float sh[5][NTHR / 32];
    #pragma unroll
    for (int k = 0; k < 5; k++) {
        float x = v[k];
        #pragma unroll
        for (int o = 16; o; o >>= 1) x += __shfl_down_sync(0xffffffffu, x, o);
        if ((tid & 31) == 0) sh[k][tid >> 5] = x;
    }
    __syncthreads();
    if (tid < 5) {
        float sm = 0.f;
        #pragma unroll
        for (int j = 0; j < NTHR / 32; j++) sm += sh[tid][j];
        g_part[tid][bid] = sm;
    }

    // ---- last-block-done finalize (deterministic fixed-order re-reduce) ----
    __shared__ int is_last;
    __threadfence();
    if (tid == 0) {
        int prev = atomicAdd(&g_count, 1);
        is_last = (prev == NBLK - 1);
    }
    __syncthreads();
    if (!is_last) return;
    __threadfence();

    float v5[5] = {0.f, 0.f, 0.f, 0.f, 0.f};
    for (int i = tid; i < NBLK; i += NTHR) {
        #pragma unroll
        for (int k = 0; k < 5; k++) v5[k] += g_part[k][i];
    }
    __shared__ float shf[5][NTHR / 32];
    #pragma unroll
    for (int k = 0; k < 5; k++) {
        float x = v5[k];
        #pragma unroll
        for (int o = 16; o; o >>= 1) x += __shfl_down_sync(0xffffffffu, x, o);
        if ((tid & 31) == 0) shf[k][tid >> 5] = x;
    }
    __syncthreads();
    if (tid == 0) {
        double t[5];
        #pragma unroll
        for (int k = 0; k < 5; k++) {
            float sm = 0.f;
            #pragma unroll
            for (int j = 0; j < NTHR / 32; j++) sm += shf[k][j];
            t[k] = (double)sm;
        }
        double Bn = (double)B;
        double single = t[0] / (3.0 * Bn);                   // S / (3B)
        out[0] = (float)((t[4] * single + t[1] / 3.0) / Bn); // label_loss
        out[1] = (float)(t[2] / Bn);                         // mae1
        out[2] = (float)(t[3] / Bn);                         // mae2
        g_count = 0;                     // reset for next graph replay
    }
}

extern "C" void kernel_launch(void* const* d_in, const int* in_sizes, int n_in,
                              void* d_out, int out_size)
{
    const float* label = (const float*)d_in[0];
    const float* est   = (const float*)d_in[1];
    const int*   mix   = (const int*)d_in[2];
    int B = in_sizes[2];  // mix_way element count

    fused_kernel<<<NBLK, NTHR>>>(label, est, mix, (float*)d_out, B);
}